// round 1
// baseline (speedup 1.0000x reference)
#include <cuda_runtime.h>
#include <cuda_bf16.h>
#include <math.h>

// Problem constants
#define BB   2
#define NN   2048
#define DIM  512
#define HH   8
#define DH   64
#define INNER 512          // H*DH
#define QKV3 1536          // 3*INNER
#define MROWS (BB*NN)      // 4096

// Scratch (device globals; no allocation allowed)
__device__ float g_qkv[MROWS * QKV3];   // 24 MB  [b*N+i][3*INNER]
__device__ float g_att[MROWS * INNER];  //  8 MB  [b*N+i][h*64+d]

// ---------------------------------------------------------------------------
// Tiled fp32 GEMM: C[M,N] = A[M,K] @ B[K,N] (+bias). BM=BN=64, BK=16, 256 thr.
// Each thread computes a 4x4 micro-tile.
// ---------------------------------------------------------------------------
__global__ __launch_bounds__(256) void gemm64(const float* __restrict__ A,
                                              const float* __restrict__ B,
                                              const float* __restrict__ bias,
                                              float* __restrict__ C,
                                              int M, int N, int K)
{
    __shared__ float As[16][65];   // transposed: As[k][m]
    __shared__ float Bs[16][64];   // Bs[k][n]

    const int bm = blockIdx.y * 64;
    const int bn = blockIdx.x * 64;
    const int tid = threadIdx.x;
    const int tx = tid & 15;          // 0..15 -> n
    const int ty = tid >> 4;          // 0..15 -> m

    float acc[4][4];
#pragma unroll
    for (int i = 0; i < 4; i++)
#pragma unroll
        for (int j = 0; j < 4; j++) acc[i][j] = 0.0f;

    for (int k0 = 0; k0 < K; k0 += 16) {
        // load A tile (64 rows x 16 k) as float4, store transposed
        {
            const int m  = tid >> 2;            // 0..63
            const int kq = (tid & 3) * 4;       // 0,4,8,12
            float4 a = *reinterpret_cast<const float4*>(&A[(size_t)(bm + m) * K + k0 + kq]);
            As[kq + 0][m] = a.x;
            As[kq + 1][m] = a.y;
            As[kq + 2][m] = a.z;
            As[kq + 3][m] = a.w;
        }
        // load B tile (16 k x 64 n) as float4
        {
            const int k  = tid >> 4;            // 0..15
            const int n4 = (tid & 15) * 4;      // 0..60
            float4 b = *reinterpret_cast<const float4*>(&B[(size_t)(k0 + k) * N + bn + n4]);
            Bs[k][n4 + 0] = b.x;
            Bs[k][n4 + 1] = b.y;
            Bs[k][n4 + 2] = b.z;
            Bs[k][n4 + 3] = b.w;
        }
        __syncthreads();

#pragma unroll
        for (int kk = 0; kk < 16; kk++) {
            float a[4], b[4];
#pragma unroll
            for (int i = 0; i < 4; i++) a[i] = As[kk][ty * 4 + i];
#pragma unroll
            for (int j = 0; j < 4; j++) b[j] = Bs[kk][tx * 4 + j];
#pragma unroll
            for (int i = 0; i < 4; i++)
#pragma unroll
                for (int j = 0; j < 4; j++) acc[i][j] = fmaf(a[i], b[j], acc[i][j]);
        }
        __syncthreads();
    }

#pragma unroll
    for (int i = 0; i < 4; i++) {
        const int row = bm + ty * 4 + i;
#pragma unroll
        for (int j = 0; j < 4; j++) {
            const int col = bn + tx * 4 + j;
            float v = acc[i][j];
            if (bias) v += bias[col];
            C[(size_t)row * N + col] = v;
        }
    }
}

// ---------------------------------------------------------------------------
// Flash-style masked attention.
// grid = (N/64, B*H); block = 256 threads. Each block: 64 q-rows of one (b,h).
// Dynamic smem: Qs[64][64], Ks[64][65], Vs[64][65], Ps[64][65].
// ---------------------------------------------------------------------------
#define ATT_SMEM_FLOATS (64*64 + 3*64*65)
#define ATT_SMEM_BYTES  (ATT_SMEM_FLOATS * 4)

__global__ __launch_bounds__(256) void attn_kernel(const float* __restrict__ qkv,
                                                   const int* __restrict__ mask_np,
                                                   const int* __restrict__ mask_bert,
                                                   float* __restrict__ out)
{
    extern __shared__ float sm[];
    float* Qs = sm;                      // [64][64]
    float* Ks = sm + 64 * 64;            // [64][65]   (reused as P after scores)
    float* Vs = Ks + 64 * 65;            // [64][65]
    float* Ps = Vs + 64 * 65;            // [64][65]
    __shared__ int mnpk[64];
    __shared__ int mbk[64];

    const int b  = blockIdx.y >> 3;
    const int h  = blockIdx.y & 7;
    const int q0 = blockIdx.x * 64;
    const int tid = threadIdx.x;
    const int tx = tid & 15;             // key-col group (4 cols)
    const int ty = tid >> 4;             // q-row group (4 rows)
    const float scale = 0.125f;          // 1/sqrt(64)

    // load Q tile: rows q0..q0+63, dims h*64..h*64+63
#pragma unroll
    for (int it = 0; it < 4; it++) {
        int lin = it * 256 + tid;
        int r = lin >> 4;
        int d4 = (lin & 15) * 4;
        float4 q = *reinterpret_cast<const float4*>(
            &qkv[((size_t)(b * NN + q0 + r)) * QKV3 + h * 64 + d4]);
        *reinterpret_cast<float4*>(&Qs[r * 64 + d4]) = q;
    }

    // per-thread row masks (mask_np for q rows)
    int mi[4];
#pragma unroll
    for (int i = 0; i < 4; i++) mi[i] = mask_np[b * NN + q0 + ty * 4 + i];

    float O[4][4];
    float m_r[4], l_r[4];
#pragma unroll
    for (int i = 0; i < 4; i++) {
        m_r[i] = -1e30f; l_r[i] = 0.0f;
#pragma unroll
        for (int j = 0; j < 4; j++) O[i][j] = 0.0f;
    }

    for (int t = 0; t < NN / 64; t++) {
        const int k0 = t * 64;
        __syncthreads();   // prev AV done before overwriting K/V/P

        // load K and V tiles
#pragma unroll
        for (int it = 0; it < 4; it++) {
            int lin = it * 256 + tid;
            int r = lin >> 4;
            int d4 = (lin & 15) * 4;
            size_t base = ((size_t)(b * NN + k0 + r)) * QKV3 + h * 64 + d4;
            float4 kv = *reinterpret_cast<const float4*>(&qkv[base + INNER]);
            Ks[r * 65 + d4 + 0] = kv.x;
            Ks[r * 65 + d4 + 1] = kv.y;
            Ks[r * 65 + d4 + 2] = kv.z;
            Ks[r * 65 + d4 + 3] = kv.w;
            float4 vv = *reinterpret_cast<const float4*>(&qkv[base + 2 * INNER]);
            Vs[r * 65 + d4 + 0] = vv.x;
            Vs[r * 65 + d4 + 1] = vv.y;
            Vs[r * 65 + d4 + 2] = vv.z;
            Vs[r * 65 + d4 + 3] = vv.w;
        }
        if (tid < 64) {
            mnpk[tid] = mask_np[b * NN + k0 + tid];
            mbk[tid]  = mask_bert[b * NN + k0 + tid];
        }
        __syncthreads();

        // scores: s[i][j] = Q[row ty*4+i] . K[col tx*4+j]
        float s[4][4];
#pragma unroll
        for (int i = 0; i < 4; i++)
#pragma unroll
            for (int j = 0; j < 4; j++) s[i][j] = 0.0f;

#pragma unroll 8
        for (int kk = 0; kk < 64; kk++) {
            float a[4], kb[4];
#pragma unroll
            for (int i = 0; i < 4; i++) a[i] = Qs[(ty * 4 + i) * 64 + kk];
#pragma unroll
            for (int j = 0; j < 4; j++) kb[j] = Ks[(tx * 4 + j) * 65 + kk];
#pragma unroll
            for (int i = 0; i < 4; i++)
#pragma unroll
                for (int j = 0; j < 4; j++) s[i][j] = fmaf(a[i], kb[j], s[i][j]);
        }

        // mask + scale
#pragma unroll
        for (int j = 0; j < 4; j++) {
            const int kc = tx * 4 + j;
            const bool colbad = (mnpk[kc] == 0) | (mbk[kc] == 1);
#pragma unroll
            for (int i = 0; i < 4; i++) {
                bool masked = colbad | (mi[i] == 0);
                s[i][j] = masked ? -1000.0f : s[i][j] * scale;
            }
        }

        // online softmax (row reductions across the 16 tx lanes)
        float p[4][4];
        float alpha[4];
#pragma unroll
        for (int i = 0; i < 4; i++) {
            float mx = fmaxf(fmaxf(s[i][0], s[i][1]), fmaxf(s[i][2], s[i][3]));
#pragma unroll
            for (int off = 8; off >= 1; off >>= 1)
                mx = fmaxf(mx, __shfl_xor_sync(0xffffffffu, mx, off));
            float mnew = fmaxf(m_r[i], mx);
            alpha[i] = __expf(m_r[i] - mnew);
            float ls = 0.0f;
#pragma unroll
            for (int j = 0; j < 4; j++) {
                p[i][j] = __expf(s[i][j] - mnew);
                ls += p[i][j];
            }
#pragma unroll
            for (int off = 8; off >= 1; off >>= 1)
                ls += __shfl_xor_sync(0xffffffffu, ls, off);
            l_r[i] = l_r[i] * alpha[i] + ls;
            m_r[i] = mnew;
#pragma unroll
            for (int j = 0; j < 4; j++) O[i][j] *= alpha[i];
        }

        // publish P tile
#pragma unroll
        for (int i = 0; i < 4; i++)
#pragma unroll
            for (int j = 0; j < 4; j++)
                Ps[(ty * 4 + i) * 65 + tx * 4 + j] = p[i][j];
        __syncthreads();

        // O += P @ V
#pragma unroll 8
        for (int c = 0; c < 64; c++) {
            float pv[4], vv[4];
#pragma unroll
            for (int i = 0; i < 4; i++) pv[i] = Ps[(ty * 4 + i) * 65 + c];
#pragma unroll
            for (int j = 0; j < 4; j++) vv[j] = Vs[c * 65 + tx * 4 + j];
#pragma unroll
            for (int i = 0; i < 4; i++)
#pragma unroll
                for (int j = 0; j < 4; j++) O[i][j] = fmaf(pv[i], vv[j], O[i][j]);
        }
    }

    // normalize + write [b][i][h*64+d]
#pragma unroll
    for (int i = 0; i < 4; i++) {
        const int row = q0 + ty * 4 + i;
        const float inv_l = 1.0f / l_r[i];
#pragma unroll
        for (int j = 0; j < 4; j++) {
            out[((size_t)(b * NN + row)) * INNER + h * 64 + tx * 4 + j] = O[i][j] * inv_l;
        }
    }
}

// ---------------------------------------------------------------------------
extern "C" void kernel_launch(void* const* d_in, const int* in_sizes, int n_in,
                              void* d_out, int out_size)
{
    const float* x     = (const float*)d_in[0];
    const int*   mnp   = (const int*)d_in[1];
    const int*   mbert = (const int*)d_in[2];
    const float* Wqkv  = (const float*)d_in[3];
    const float* Wout  = (const float*)d_in[4];
    const float* bout  = (const float*)d_in[5];
    float* out = (float*)d_out;

    float *qkv_ptr, *att_ptr;
    cudaGetSymbolAddress((void**)&qkv_ptr, g_qkv);
    cudaGetSymbolAddress((void**)&att_ptr, g_att);

    cudaFuncSetAttribute(attn_kernel, cudaFuncAttributeMaxDynamicSharedMemorySize,
                         ATT_SMEM_BYTES);

    // 1) qkv = x @ W_qkv
    gemm64<<<dim3(QKV3 / 64, MROWS / 64), 256>>>(x, Wqkv, nullptr, qkv_ptr,
                                                 MROWS, QKV3, DIM);
    // 2) masked flash attention
    attn_kernel<<<dim3(NN / 64, BB * HH), 256, ATT_SMEM_BYTES>>>(qkv_ptr, mnp, mbert,
                                                                 att_ptr);
    // 3) out = att @ W_out + b_out
    gemm64<<<dim3(DIM / 64, MROWS / 64), 256>>>(att_ptr, Wout, bout, out,
                                                MROWS, DIM, INNER);
}